// round 5
// baseline (speedup 1.0000x reference)
#include <cuda_runtime.h>

#define HD     64
#define VOC    64
#define HALF   32
#define BATCH  128
#define SEQLEN 2048

// ---- scratch tables (device globals; no allocation allowed) ----
__device__ float  g_ks[VOC * HALF];
__device__ float  g_ke[VOC * HALF];
__device__ float  g_inv_s[VOC];
__device__ float  g_inv_e[VOC];
__device__ float  g_Ds[VOC * VOC];    // D[v1][v2] = ks(v1) . ks(v2)
__device__ float  g_De[VOC * VOC];    // D[v1][v2] = ke(v1) . ke(v2)
__device__ float2 g_kiv_s[VOC * HALF]; // (kown, inv) fused per (tok,row)
__device__ float2 g_kiv_e[VOC * HALF];

typedef unsigned long long u64;

// Packed f32x2 ops (Blackwell FFMA2 path — only reachable via PTX)
__device__ __forceinline__ u64 ffma2(u64 a, u64 b, u64 c) {
    u64 d;
    asm("fma.rn.f32x2 %0, %1, %2, %3;" : "=l"(d) : "l"(a), "l"(b), "l"(c));
    return d;
}
__device__ __forceinline__ u64 fadd2(u64 a, u64 b) {
    u64 d;
    asm("add.rn.f32x2 %0, %1, %2;" : "=l"(d) : "l"(a), "l"(b));
    return d;
}
__device__ __forceinline__ u64 pack2(float x, float y) {
    u64 r;
    asm("mov.b64 %0, {%1, %2};" : "=l"(r) : "f"(x), "f"(y));
    return r;
}
__device__ __forceinline__ float2 unpack2(u64 v) {
    float x, y;
    asm("mov.b64 {%0, %1}, %2;" : "=f"(x), "=f"(y) : "l"(v));
    return make_float2(x, y);
}

// ============================================================================
// Kernel A: per-vocab-id table precompute (h depends only on token id).
// ============================================================================
__global__ void precompute_kernel(
    const float* __restrict__ embed,
    const float* __restrict__ W1, const float* __restrict__ b1,
    const float* __restrict__ W2, const float* __restrict__ b2,
    const float* __restrict__ ln_g, const float* __restrict__ ln_b,
    const float* __restrict__ Ws, const float* __restrict__ bs,
    const float* __restrict__ We, const float* __restrict__ be)
{
    const int v = blockIdx.x;
    const int t = threadIdx.x;

    __shared__ float s_e[HD];
    __shared__ float s_a[2 * HD];
    __shared__ float s_x[HD];
    __shared__ float s_h[HD];
    __shared__ float s_kv[2 * HALF];

    if (t < HD) s_e[t] = embed[v * HD + t];
    __syncthreads();

    {   // hidden = relu(e @ W1 + b1), 128 units, one per thread
        float acc = b1[t];
        #pragma unroll
        for (int d = 0; d < HD; d++)
            acc = fmaf(s_e[d], W1[d * (2 * HD) + t], acc);
        s_a[t] = fmaxf(acc, 0.0f);
    }
    __syncthreads();

    if (t < HD) {   // ff = hidden @ W2 + b2 ; x = e + ff
        float f = b2[t];
        #pragma unroll
        for (int k = 0; k < 2 * HD; k++)
            f = fmaf(s_a[k], W2[k * HD + t], f);
        s_x[t] = s_e[t] + f;
    }
    __syncthreads();

    if (t < HD) {   // LayerNorm (redundant per thread — tiny)
        float mu = 0.0f;
        #pragma unroll
        for (int d = 0; d < HD; d++) mu += s_x[d];
        mu *= (1.0f / HD);
        float var = 0.0f;
        #pragma unroll
        for (int d = 0; d < HD; d++) {
            float dd = s_x[d] - mu;
            var = fmaf(dd, dd, var);
        }
        var *= (1.0f / HD);
        float r = 1.0f / sqrtf(var + 1e-5f);
        s_h[t] = fmaf((s_x[t] - mu) * r, ln_g[t], ln_b[t]);
    }
    __syncthreads();

    if (t < HALF) {             // k_sem = h @ Ws + bs
        float k = bs[t];
        #pragma unroll
        for (int d = 0; d < HD; d++)
            k = fmaf(s_h[d], Ws[d * HALF + t], k);
        g_ks[v * HALF + t] = k;
        s_kv[t] = k;
    } else if (t < 2 * HALF) {  // k_epi = h @ We + be
        const int j = t - HALF;
        float k = be[j];
        #pragma unroll
        for (int d = 0; d < HD; d++)
            k = fmaf(s_h[d], We[d * HALF + j], k);
        g_ke[v * HALF + j] = k;
        s_kv[t] = k;
    }
    __syncthreads();

    if (t == 0) {               // 1/(k.k + 1e-6)
        float den = 1e-6f;
        #pragma unroll
        for (int j = 0; j < HALF; j++) den = fmaf(s_kv[j], s_kv[j], den);
        g_inv_s[v] = 1.0f / den;
    } else if (t == 1) {
        float den = 1e-6f;
        #pragma unroll
        for (int j = 0; j < HALF; j++) den = fmaf(s_kv[HALF + j], s_kv[HALF + j], den);
        g_inv_e[v] = 1.0f / den;
    }
}

// ============================================================================
// Kernel A2: token-pair dot tables + fused (kown, inv) tables.
// ============================================================================
__global__ void dots_kernel()
{
    const int v1  = blockIdx.x;
    const int tid = threadIdx.x;
    const int v2  = tid & 63;
    const int mem = tid >> 6;

    const float* tab = mem ? g_ke : g_ks;
    float d = 0.0f;
    #pragma unroll
    for (int j = 0; j < HALF; j++)
        d = fmaf(tab[v1 * HALF + j], tab[v2 * HALF + j], d);
    (mem ? g_De : g_Ds)[v1 * VOC + v2] = d;

    if (tid < HALF) {
        g_kiv_s[v1 * HALF + tid] = make_float2(g_ks[v1 * HALF + tid], g_inv_s[v1]);
    } else if (tid < 2 * HALF) {
        const int r = tid - HALF;
        g_kiv_e[v1 * HALF + r] = make_float2(g_ke[v1 * HALF + r], g_inv_e[v1]);
    }
}

// ============================================================================
// Kernel B: the scan, blocked T=4, 8 warps/block (2 per SMSP for latency
// hiding). Warps 0-3 -> M_sem, 4-7 -> M_epi. Each warp owns 8 rows x 32 cols;
// 4 lanes per row, lane&3 = 8-column quarter (4 u64 of M per lane).
// Per 4-token block:
//   P_i = M_0 @ k_i                       (4 independent matvecs)
//   vps_i = P_i + sum_{j<i} u_j D[v_j][v_i]  (row-parallel triangular solve)
//   u_i = fma(-vps_i, inv_i*w_i, kown_i*w_i)
//   M  += sum_i u_i (x) k_i
// Last block's vps_3 (position 2047) IS ctx = M_2046 @ q.
// ============================================================================
__global__ void __launch_bounds__(256, 1) scan_kernel(
    const int* __restrict__ seq,
    const float* __restrict__ Wo,
    const float* __restrict__ bo,
    float* __restrict__ out)
{
    extern __shared__ int smem_raw[];
    int*    s_toko = smem_raw;                         // 2048 ints (byte offs)
    float*  s_k    = (float*)(s_toko + SEQLEN);        // 2 * 2048 floats
    float*  s_D    = s_k + 2 * VOC * HALF;             // 2 * 4096 floats
    float2* s_kiv  = (float2*)(s_D + 2 * VOC * VOC);   // 2 * 2048 float2
    float*  s_ctx  = (float*)(s_kiv + 2 * VOC * HALF); // 64 floats

    const int b    = blockIdx.x;
    const int tid  = threadIdx.x;
    const int wid  = tid >> 5;
    const int lane = tid & 31;
    const int mem  = wid >> 2;            // 0 = sem, 1 = epi
    const int wq   = wid & 3;             // row-group within the memory
    const int row  = wq * 8 + (lane >> 2);
    const int q    = lane & 3;            // 8-column quarter

    for (int i = tid; i < SEQLEN; i += 256)
        s_toko[i] = seq[b * SEQLEN + i] << 7;          // byte offset tok*128
    for (int i = tid; i < VOC * HALF; i += 256) {
        s_k[i]              = g_ks[i];
        s_k[VOC * HALF + i] = g_ke[i];
        s_kiv[i]              = g_kiv_s[i];
        s_kiv[VOC * HALF + i] = g_kiv_e[i];
    }
    for (int i = tid; i < VOC * VOC; i += 256) {
        s_D[i]             = g_Ds[i];
        s_D[VOC * VOC + i] = g_De[i];
    }
    __syncthreads();

    const char* kb_q  = (const char*)(s_k + mem * (VOC * HALF)) + q * 32;
    const char* kivb  = (const char*)(s_kiv + mem * (VOC * HALF)) + row * 8;
    const char* Db    = (const char*)(s_D + mem * (VOC * VOC));
    const int4* s_tok4 = (const int4*)s_toko;          // 512 packs

    const u64 zero64 = 0ull;
    u64 m[4];
    #pragma unroll
    for (int j = 0; j < 4; j++) m[j] = 0ull;

    // recency weight: epi w_t = (t+1)/2048 (update only); sem w = 1
    const float wstep = mem ? (1.0f / 2048.0f) : 0.0f;
    float wt = mem ? (1.0f / 2048.0f) : 1.0f;          // weight of token 4*blk

    float ctxv = 0.0f;

    for (int blk = 0; blk < SEQLEN / 4; blk++) {
        const int4 off4 = s_tok4[blk];
        const int o0 = off4.x, o1 = off4.y, o2 = off4.z, o3 = off4.w;

        // ---- k tiles: this lane's 8-col quarter of each token's k (2x LDS.128)
        u64 k0[4], k1[4], k2[4], k3[4];
        {
            const char* p0 = kb_q + o0; const char* p1 = kb_q + o1;
            const char* p2 = kb_q + o2; const char* p3 = kb_q + o3;
            ulonglong2 x0 = *(const ulonglong2*)(p0);
            ulonglong2 y0 = *(const ulonglong2*)(p0 + 16);
            ulonglong2 x1 = *(const ulonglong2*)(p1);
            ulonglong2 y1 = *(const ulonglong2*)(p1 + 16);
            ulonglong2 x2 = *(const ulonglong2*)(p2);
            ulonglong2 y2 = *(const ulonglong2*)(p2 + 16);
            ulonglong2 x3 = *(const ulonglong2*)(p3);
            ulonglong2 y3 = *(const ulonglong2*)(p3 + 16);
            k0[0] = x0.x; k0[1] = x0.y; k0[2] = y0.x; k0[3] = y0.y;
            k1[0] = x1.x; k1[1] = x1.y; k1[2] = y1.x; k1[3] = y1.y;
            k2[0] = x2.x; k2[1] = x2.y; k2[2] = y2.x; k2[3] = y2.y;
            k3[0] = x3.x; k3[1] = x3.y; k3[2] = y3.x; k3[3] = y3.y;
        }

        // ---- fused (kown, inv) per token for this lane's row (LDS.64)
        const float2 kv0 = *(const float2*)(kivb + (o0 << 1));
        const float2 kv1 = *(const float2*)(kivb + (o1 << 1));
        const float2 kv2 = *(const float2*)(kivb + (o2 << 1));
        const float2 kv3 = *(const float2*)(kivb + (o3 << 1));

        // ---- D-table entries for within-block interactions
        const float D01 = *(const float*)(Db + (o0 << 1) + (o1 >> 5));
        const float D02 = *(const float*)(Db + (o0 << 1) + (o2 >> 5));
        const float D03 = *(const float*)(Db + (o0 << 1) + (o3 >> 5));
        const float D12 = *(const float*)(Db + (o1 << 1) + (o2 >> 5));
        const float D13 = *(const float*)(Db + (o1 << 1) + (o3 >> 5));
        const float D23 = *(const float*)(Db + (o2 << 1) + (o3 >> 5));

        const float w0 = wt;
        const float w1 = w0 + wstep;
        const float w2 = w1 + wstep;
        const float w3 = w2 + wstep;
        wt = w3 + wstep;
        const float kw0 = kv0.x * w0, iw0 = kv0.y * w0;
        const float kw1 = kv1.x * w1, iw1 = kv1.y * w1;
        const float kw2 = kv2.x * w2, iw2 = kv2.y * w2;
        const float kw3 = kv3.x * w3, iw3 = kv3.y * w3;

        // ---- phase 1: P_i = M_0 @ k_i (4 independent matvecs, 2 accums each)
        u64 a0 = ffma2(m[0], k0[0], zero64), b0 = ffma2(m[1], k0[1], zero64);
        u64 a1 = ffma2(m[0], k1[0], zero64), b1 = ffma2(m[1], k1[1], zero64);
        u64 a2 = ffma2(m[0], k2[0], zero64), b2 = ffma2(m[1], k2[1], zero64);
        u64 a3 = ffma2(m[0], k3[0], zero64), b3 = ffma2(m[1], k3[1], zero64);
        a0 = ffma2(m[2], k0[2], a0); b0 = ffma2(m[3], k0[3], b0);
        a1 = ffma2(m[2], k1[2], a1); b1 = ffma2(m[3], k1[3], b1);
        a2 = ffma2(m[2], k2[2], a2); b2 = ffma2(m[3], k2[3], b2);
        a3 = ffma2(m[2], k3[2], a3); b3 = ffma2(m[3], k3[3], b3);
        float2 r0 = unpack2(fadd2(a0, b0));
        float2 r1 = unpack2(fadd2(a1, b1));
        float2 r2 = unpack2(fadd2(a2, b2));
        float2 r3 = unpack2(fadd2(a3, b3));
        float p0 = r0.x + r0.y;
        float p1 = r1.x + r1.y;
        float p2 = r2.x + r2.y;
        float p3 = r3.x + r3.y;
        // reduce across the 4 lanes of this row (lane bits 0-1)
        p0 += __shfl_xor_sync(0xffffffffu, p0, 1);
        p1 += __shfl_xor_sync(0xffffffffu, p1, 1);
        p2 += __shfl_xor_sync(0xffffffffu, p2, 1);
        p3 += __shfl_xor_sync(0xffffffffu, p3, 1);
        p0 += __shfl_xor_sync(0xffffffffu, p0, 2);
        p1 += __shfl_xor_sync(0xffffffffu, p1, 2);
        p2 += __shfl_xor_sync(0xffffffffu, p2, 2);
        p3 += __shfl_xor_sync(0xffffffffu, p3, 2);

        // ---- phase 2: triangular solve (row-parallel scalars)
        const float u0 = fmaf(-p0, iw0, kw0);
        float vps1 = fmaf(u0, D01, p1);
        const float u1 = fmaf(-vps1, iw1, kw1);
        float vps2 = fmaf(u0, D02, p2);
        vps2 = fmaf(u1, D12, vps2);
        const float u2 = fmaf(-vps2, iw2, kw2);
        float vps3 = fmaf(u0, D03, p3);
        vps3 = fmaf(u1, D13, vps3);
        vps3 = fmaf(u2, D23, vps3);
        const float u3 = fmaf(-vps3, iw3, kw3);
        ctxv = vps3;                      // last block: = (M_2046 @ q)[row]

        // ---- phase 3: M += sum_i u_i (x) k_i
        const u64 U0 = pack2(u0, u0);
        const u64 U1 = pack2(u1, u1);
        const u64 U2 = pack2(u2, u2);
        const u64 U3 = pack2(u3, u3);
        #pragma unroll
        for (int j = 0; j < 4; j++) {
            u64 t0 = ffma2(U0, k0[j], m[j]);
            t0 = ffma2(U1, k1[j], t0);
            t0 = ffma2(U2, k2[j], t0);
            m[j] = ffma2(U3, k3[j], t0);
        }
    }

    // ctxv (post-shfl; all 4 lanes of a row agree) = ctx[row] for this memory.
    if (q == 0) s_ctx[mem * HALF + row] = ctxv;
    __syncthreads();

    if (tid < VOC) {
        float o = bo[tid];
        #pragma unroll
        for (int i = 0; i < 2 * HALF; i++)
            o = fmaf(s_ctx[i], Wo[i * VOC + tid], o);
        out[b * VOC + tid] = o;
    }
}

// ============================================================================
// Launch. Inputs in metadata order:
// 0:seq 1:embed 2:W1 3:b1 4:W2 5:b2 6:ln_g 7:ln_b 8:Ws 9:bs 10:We 11:be 12:Wo 13:bo
// ============================================================================
#define SCAN_SMEM_BYTES ((SEQLEN + 2*VOC*HALF + 2*VOC*VOC + 4*VOC*HALF + VOC) * 4)

extern "C" void kernel_launch(void* const* d_in, const int* in_sizes, int n_in,
                              void* d_out, int out_size)
{
    const int*   seq   = (const int*)  d_in[0];
    const float* embed = (const float*)d_in[1];
    const float* W1    = (const float*)d_in[2];
    const float* b1    = (const float*)d_in[3];
    const float* W2    = (const float*)d_in[4];
    const float* b2    = (const float*)d_in[5];
    const float* ln_g  = (const float*)d_in[6];
    const float* ln_b  = (const float*)d_in[7];
    const float* Ws    = (const float*)d_in[8];
    const float* bs    = (const float*)d_in[9];
    const float* We    = (const float*)d_in[10];
    const float* be    = (const float*)d_in[11];
    const float* Wo    = (const float*)d_in[12];
    const float* bo    = (const float*)d_in[13];

    cudaFuncSetAttribute(scan_kernel,
                         cudaFuncAttributeMaxDynamicSharedMemorySize,
                         SCAN_SMEM_BYTES);

    precompute_kernel<<<VOC, 128>>>(embed, W1, b1, W2, b2, ln_g, ln_b,
                                    Ws, bs, We, be);
    dots_kernel<<<VOC, 128>>>();
    scan_kernel<<<BATCH, 256, SCAN_SMEM_BYTES>>>(seq, Wo, bo, (float*)d_out);
}

// round 6
// speedup vs baseline: 2.0494x; 2.0494x over previous
#include <cuda_runtime.h>

#define HD     64
#define VOC    64
#define HALF   32
#define BATCH  128
#define SEQLEN 2048

// ---- scratch tables (device globals; no allocation allowed) ----
__device__ __align__(16) float g_ks[VOC * HALF];
__device__ __align__(16) float g_ke[VOC * HALF];
__device__ __align__(16) float g_inv_s[VOC];
__device__ __align__(16) float g_inv_e[VOC];
__device__ __align__(16) float g_Ds[VOC * VOC];   // D[v1][v2] = ks(v1).ks(v2)
__device__ __align__(16) float g_De[VOC * VOC];   // D[v1][v2] = ke(v1).ke(v2)

// ============================================================================
// Kernel A: per-vocab-id table precompute (h depends only on token id).
// ============================================================================
__global__ void precompute_kernel(
    const float* __restrict__ embed,
    const float* __restrict__ W1, const float* __restrict__ b1,
    const float* __restrict__ W2, const float* __restrict__ b2,
    const float* __restrict__ ln_g, const float* __restrict__ ln_b,
    const float* __restrict__ Ws, const float* __restrict__ bs,
    const float* __restrict__ We, const float* __restrict__ be)
{
    const int v = blockIdx.x;
    const int t = threadIdx.x;

    __shared__ float s_e[HD];
    __shared__ float s_a[2 * HD];
    __shared__ float s_x[HD];
    __shared__ float s_h[HD];
    __shared__ float s_kv[2 * HALF];

    if (t < HD) s_e[t] = embed[v * HD + t];
    __syncthreads();

    {   // hidden = relu(e @ W1 + b1), 128 units, one per thread
        float acc = b1[t];
        #pragma unroll
        for (int d = 0; d < HD; d++)
            acc = fmaf(s_e[d], W1[d * (2 * HD) + t], acc);
        s_a[t] = fmaxf(acc, 0.0f);
    }
    __syncthreads();

    if (t < HD) {   // ff = hidden @ W2 + b2 ; x = e + ff
        float f = b2[t];
        #pragma unroll
        for (int k = 0; k < 2 * HD; k++)
            f = fmaf(s_a[k], W2[k * HD + t], f);
        s_x[t] = s_e[t] + f;
    }
    __syncthreads();

    if (t < HD) {   // LayerNorm (redundant per thread — tiny)
        float mu = 0.0f;
        #pragma unroll
        for (int d = 0; d < HD; d++) mu += s_x[d];
        mu *= (1.0f / HD);
        float var = 0.0f;
        #pragma unroll
        for (int d = 0; d < HD; d++) {
            float dd = s_x[d] - mu;
            var = fmaf(dd, dd, var);
        }
        var *= (1.0f / HD);
        float r = 1.0f / sqrtf(var + 1e-5f);
        s_h[t] = fmaf((s_x[t] - mu) * r, ln_g[t], ln_b[t]);
    }
    __syncthreads();

    if (t < HALF) {             // k_sem = h @ Ws + bs
        float k = bs[t];
        #pragma unroll
        for (int d = 0; d < HD; d++)
            k = fmaf(s_h[d], Ws[d * HALF + t], k);
        g_ks[v * HALF + t] = k;
        s_kv[t] = k;
    } else if (t < 2 * HALF) {  // k_epi = h @ We + be
        const int j = t - HALF;
        float k = be[j];
        #pragma unroll
        for (int d = 0; d < HD; d++)
            k = fmaf(s_h[d], We[d * HALF + j], k);
        g_ke[v * HALF + j] = k;
        s_kv[t] = k;
    }
    __syncthreads();

    if (t == 0) {               // 1/(k.k + 1e-6)
        float den = 1e-6f;
        #pragma unroll
        for (int j = 0; j < HALF; j++) den = fmaf(s_kv[j], s_kv[j], den);
        g_inv_s[v] = 1.0f / den;
    } else if (t == 1) {
        float den = 1e-6f;
        #pragma unroll
        for (int j = 0; j < HALF; j++) den = fmaf(s_kv[HALF + j], s_kv[HALF + j], den);
        g_inv_e[v] = 1.0f / den;
    }
}

// ============================================================================
// Kernel A2: token-pair dot tables D[v1][v2] = k(v1).k(v2) per memory.
// ============================================================================
__global__ void dots_kernel()
{
    const int v1  = blockIdx.x;
    const int tid = threadIdx.x;
    const int v2  = tid & 63;
    const int mem = tid >> 6;

    const float* tab = mem ? g_ke : g_ks;
    float d = 0.0f;
    #pragma unroll
    for (int j = 0; j < HALF; j++)
        d = fmaf(tab[v1 * HALF + j], tab[v2 * HALF + j], d);
    (mem ? g_De : g_Ds)[v1 * VOC + v2] = d;
}

// ============================================================================
// Kernel B: backward adjoint scan — the matrix never materializes.
//
// M_t = M_{t-1} A_t + B_t,  A_t = I - w_t inv_t k_t k_t^T,  B_t = w_t k_t k_t^T.
// ctx = M_2046 q = sum_t w_t (k_t . z_t) k_t,   z_t = (A_{t+1}...A_2046) q.
// z_t = q - sum_{s>t} dd_s k_s  with dd_s = w_s inv_s d_s, d_s = k_s . z_s.
// Since q = k(v_2047):  d_t = D[v_t, v_q] - S_{t+1}[v_t]  where
//   S_tau[v] = sum_{s>=tau} dd_s D[v_s, v]   (64 scalars, 2 per lane).
// Per token: 1 shfl.idx (S[v], lagged 2 iters with two D-correction FMAs),
// 3-FMA critical chain, one D-row axpy into S, ctx += wd * k[v][lane].
//
// 128 blocks (one per batch) x 64 threads: warp 0 = sem, warp 1 = epi
// (distinct SMSPs). Output projection fused at the end of the block.
// ============================================================================
__global__ void __launch_bounds__(64, 1) scan_kernel(
    const int* __restrict__ seq,
    const float* __restrict__ Wo,
    const float* __restrict__ bo,
    float* __restrict__ out)
{
    extern __shared__ int smem_raw[];
    int*   s_tok = smem_raw;                  // 2048 ints, pre-shifted <<7
    float* s_k   = (float*)(s_tok + SEQLEN);  // 2 * 2048
    float* s_D   = s_k + 2 * VOC * HALF;      // 2 * 4096
    float* s_inv = s_D + 2 * VOC * VOC;       // 2 * 64
    float* s_ctx = s_inv + 2 * VOC;           // 64

    const int b    = blockIdx.x;
    const int tid  = threadIdx.x;
    const int mem  = tid >> 5;                // warp 0 = sem, warp 1 = epi
    const int lane = tid & 31;

    // ---- preamble: fill shared tables (both warps cooperate) ----
    {
        const int4* seq4 = (const int4*)(seq + b * SEQLEN);
        int4* tok4 = (int4*)s_tok;
        for (int i = tid; i < SEQLEN / 4; i += 64) {
            int4 v = seq4[i];
            v.x <<= 7; v.y <<= 7; v.z <<= 7; v.w <<= 7;
            tok4[i] = v;
        }
        float4* k4  = (float4*)s_k;
        const float4* gks4 = (const float4*)g_ks;
        const float4* gke4 = (const float4*)g_ke;
        for (int i = tid; i < VOC * HALF / 4; i += 64) {
            k4[i]                    = gks4[i];
            k4[VOC * HALF / 4 + i]   = gke4[i];
        }
        float4* D4 = (float4*)s_D;
        const float4* gDs4 = (const float4*)g_Ds;
        const float4* gDe4 = (const float4*)g_De;
        for (int i = tid; i < VOC * VOC / 4; i += 64) {
            D4[i]                  = gDs4[i];
            D4[VOC * VOC / 4 + i]  = gDe4[i];
        }
        if (tid < VOC) {
            s_inv[tid]       = g_inv_s[tid];
            s_inv[VOC + tid] = g_inv_e[tid];
        }
    }
    __syncthreads();

    // byte-offset bases for this memory
    const char* Db  = (const char*)(s_D + mem * (VOC * VOC)); // + (v<<1 of o) + col
    const char* kb  = (const char*)(s_k + mem * (VOC * HALF)) + lane * 4;
    const char* ivb = (const char*)(s_inv + mem * VOC);
    const char* Drb = (const char*)(s_D + mem * (VOC * VOC)) + lane * 8;

    const int vq4 = s_tok[SEQLEN - 1] >> 5;   // query column byte offset

    // recency weight, descending: epi w_t = (t+1)/2048; sem w = 1
    const float winc = mem ? (1.0f / 2048.0f) : 0.0f;
    float wt = mem ? (2047.0f / 2048.0f) : 1.0f;

    // ---- prologue (state entering iteration t = 2046) ----
    int o1  = s_tok[2047];
    int o0  = s_tok[2046];
    int om1 = s_tok[2045];

    float kl0  = *(const float*)(kb + o0);
    float klm1 = *(const float*)(kb + om1);
    float iv0  = *(const float*)(ivb + (o0 >> 5));
    float ivm1 = *(const float*)(ivb + (om1 >> 5));
    float Dq_m1 = *(const float*)(Db + (om1 << 1) + vq4);
    float pre0  = *(const float*)(Db + (o0 << 1) + vq4);  // Dq[v_2046]

    float R_m1 = 0.0f;     // S_{2048}[v_2045] = 0
    float dd_lag = 0.0f;   // dd_{2047} = 0
    float Slo = 0.0f, Shi = 0.0f;
    float ctx = 0.0f;

    #pragma unroll 4
    for (int t = 2046; t >= 0; --t) {
        // ---- (a) token t-2: issue S lookup on PRE-update S (= S_{t+1}) ----
        int tm2 = t - 2;
        tm2 = tm2 < 0 ? 0 : tm2;
        const int om2 = s_tok[tm2];
        const int par = (om2 >> 7) & 1;       // v & 1   (uniform)
        const int src = om2 >> 8;             // v >> 1  (uniform)
        const float sv  = par ? Shi : Slo;
        const float R_m2 = __shfl_sync(0xffffffffu, sv, src);

        // prefetch token t-2 scalars
        const float Dq_m2 = *(const float*)(Db + (om2 << 1) + vq4);
        const float klm2  = *(const float*)(kb + om2);
        const float ivm2  = *(const float*)(ivb + (om2 >> 5));

        // D entries for this iteration (row v_{t+1})
        const int r1 = o1 << 1;
        const float Dc = *(const float*)(Db + r1 + (o0 >> 5));   // D[v_{t+1},v_t]
        const float Dbx = *(const float*)(Db + r1 + (om1 >> 5)); // D[v_{t+1},v_{t-1}]
        const float2 Drow = *(const float2*)(Drb + (o0 << 1));   // D[v_t][2l,2l+1]

        // ---- (c) finalize token t ----
        const float d  = fmaf(-dd_lag, Dc, pre0);
        const float wd = d * wt;
        const float dd = wd * iv0;
        ctx = fmaf(wd, kl0, ctx);

        // ---- (b) pre for token t-1 ----
        const float pre_m1 = fmaf(-dd_lag, Dbx, Dq_m1 - R_m1);

        // ---- S update (reads of Slo/Shi above use pre-update values) ----
        Slo = fmaf(dd, Drow.x, Slo);
        Shi = fmaf(dd, Drow.y, Shi);

        // ---- rotate rings ----
        o1 = o0; o0 = om1; om1 = om2;
        kl0 = klm1; klm1 = klm2;
        iv0 = ivm1; ivm1 = ivm2;
        Dq_m1 = Dq_m2;
        R_m1 = R_m2;
        pre0 = pre_m1;
        dd_lag = dd;
        wt -= winc;
    }

    s_ctx[mem * HALF + lane] = ctx;
    __syncthreads();

    // out[b] = [ctx_s, ctx_e] @ Wo + bo   (64 threads, one column each)
    {
        float o = bo[tid];
        #pragma unroll
        for (int i = 0; i < 2 * HALF; i++)
            o = fmaf(s_ctx[i], Wo[i * VOC + tid], o);
        out[b * VOC + tid] = o;
    }
}

// ============================================================================
// Launch. Inputs in metadata order:
// 0:seq 1:embed 2:W1 3:b1 4:W2 5:b2 6:ln_g 7:ln_b 8:Ws 9:bs 10:We 11:be 12:Wo 13:bo
// ============================================================================
#define SCAN_SMEM_BYTES ((SEQLEN + 2*VOC*HALF + 2*VOC*VOC + 2*VOC + VOC) * 4)

extern "C" void kernel_launch(void* const* d_in, const int* in_sizes, int n_in,
                              void* d_out, int out_size)
{
    const int*   seq   = (const int*)  d_in[0];
    const float* embed = (const float*)d_in[1];
    const float* W1    = (const float*)d_in[2];
    const float* b1    = (const float*)d_in[3];
    const float* W2    = (const float*)d_in[4];
    const float* b2    = (const float*)d_in[5];
    const float* ln_g  = (const float*)d_in[6];
    const float* ln_b  = (const float*)d_in[7];
    const float* Ws    = (const float*)d_in[8];
    const float* bs    = (const float*)d_in[9];
    const float* We    = (const float*)d_in[10];
    const float* be    = (const float*)d_in[11];
    const float* Wo    = (const float*)d_in[12];
    const float* bo    = (const float*)d_in[13];

    cudaFuncSetAttribute(scan_kernel,
                         cudaFuncAttributeMaxDynamicSharedMemorySize,
                         SCAN_SMEM_BYTES);

    precompute_kernel<<<VOC, 128>>>(embed, W1, b1, W2, b2, ln_g, ln_b,
                                    Ws, bs, We, be);
    dots_kernel<<<VOC, 128>>>();
    scan_kernel<<<BATCH, 64, SCAN_SMEM_BYTES>>>(seq, Wo, bo, (float*)d_out);
}

// round 7
// speedup vs baseline: 2.1055x; 1.0273x over previous
#include <cuda_runtime.h>

#define HD     64
#define VOC    64
#define HALF   32
#define BATCH  128
#define SEQLEN 2048

// ---- scratch tables (device globals; no allocation allowed) ----
__device__ __align__(16) float g_ks[VOC * HALF];
__device__ __align__(16) float g_ke[VOC * HALF];
__device__ __align__(16) float g_inv_s[VOC];
__device__ __align__(16) float g_inv_e[VOC];
__device__ __align__(16) float g_Ds[VOC * VOC];   // D[v1][v2] = ks(v1).ks(v2)
__device__ __align__(16) float g_De[VOC * VOC];   // D[v1][v2] = ke(v1).ke(v2)

// ============================================================================
// Kernel A: per-vocab-id table precompute (h depends only on token id).
// ============================================================================
__global__ void precompute_kernel(
    const float* __restrict__ embed,
    const float* __restrict__ W1, const float* __restrict__ b1,
    const float* __restrict__ W2, const float* __restrict__ b2,
    const float* __restrict__ ln_g, const float* __restrict__ ln_b,
    const float* __restrict__ Ws, const float* __restrict__ bs,
    const float* __restrict__ We, const float* __restrict__ be)
{
    const int v = blockIdx.x;
    const int t = threadIdx.x;

    __shared__ float s_e[HD];
    __shared__ float s_a[2 * HD];
    __shared__ float s_x[HD];
    __shared__ float s_h[HD];
    __shared__ float s_kv[2 * HALF];

    if (t < HD) s_e[t] = embed[v * HD + t];
    __syncthreads();

    {   // hidden = relu(e @ W1 + b1), 128 units, one per thread
        float acc = b1[t];
        #pragma unroll
        for (int d = 0; d < HD; d++)
            acc = fmaf(s_e[d], W1[d * (2 * HD) + t], acc);
        s_a[t] = fmaxf(acc, 0.0f);
    }
    __syncthreads();

    if (t < HD) {   // ff = hidden @ W2 + b2 ; x = e + ff
        float f = b2[t];
        #pragma unroll
        for (int k = 0; k < 2 * HD; k++)
            f = fmaf(s_a[k], W2[k * HD + t], f);
        s_x[t] = s_e[t] + f;
    }
    __syncthreads();

    if (t < HD) {   // LayerNorm (redundant per thread — tiny)
        float mu = 0.0f;
        #pragma unroll
        for (int d = 0; d < HD; d++) mu += s_x[d];
        mu *= (1.0f / HD);
        float var = 0.0f;
        #pragma unroll
        for (int d = 0; d < HD; d++) {
            float dd = s_x[d] - mu;
            var = fmaf(dd, dd, var);
        }
        var *= (1.0f / HD);
        float r = 1.0f / sqrtf(var + 1e-5f);
        s_h[t] = fmaf((s_x[t] - mu) * r, ln_g[t], ln_b[t]);
    }
    __syncthreads();

    if (t < HALF) {             // k_sem = h @ Ws + bs
        float k = bs[t];
        #pragma unroll
        for (int d = 0; d < HD; d++)
            k = fmaf(s_h[d], Ws[d * HALF + t], k);
        g_ks[v * HALF + t] = k;
        s_kv[t] = k;
    } else if (t < 2 * HALF) {  // k_epi = h @ We + be
        const int j = t - HALF;
        float k = be[j];
        #pragma unroll
        for (int d = 0; d < HD; d++)
            k = fmaf(s_h[d], We[d * HALF + j], k);
        g_ke[v * HALF + j] = k;
        s_kv[t] = k;
    }
    __syncthreads();

    if (t == 0) {               // 1/(k.k + 1e-6)
        float den = 1e-6f;
        #pragma unroll
        for (int j = 0; j < HALF; j++) den = fmaf(s_kv[j], s_kv[j], den);
        g_inv_s[v] = 1.0f / den;
    } else if (t == 1) {
        float den = 1e-6f;
        #pragma unroll
        for (int j = 0; j < HALF; j++) den = fmaf(s_kv[HALF + j], s_kv[HALF + j], den);
        g_inv_e[v] = 1.0f / den;
    }
}

// ============================================================================
// Kernel A2: token-pair dot tables D[v1][v2] = k(v1).k(v2) per memory.
// ============================================================================
__global__ void dots_kernel()
{
    const int v1  = blockIdx.x;
    const int tid = threadIdx.x;
    const int v2  = tid & 63;
    const int mem = tid >> 6;

    const float* tab = mem ? g_ke : g_ks;
    float d = 0.0f;
    #pragma unroll
    for (int j = 0; j < HALF; j++)
        d = fmaf(tab[v1 * HALF + j], tab[v2 * HALF + j], d);
    (mem ? g_De : g_Ds)[v1 * VOC + v2] = d;
}

// ============================================================================
// Kernel B: backward adjoint scan (fully prefetched, 2-op critical chain).
//
// ctx = sum_t w_t d_t k(v_t),  d_t = Dq[v_t] - S_{t+1}[v_t],
// S_tau[v] = sum_{s>=tau} dd_s D[v_s, v],  dd_s = w_s inv_s d_s.
// Per iteration t (descending):
//   - shfl fetches S_{t+1}[v_{t-2}] (lagged; corrected later via D entries)
//   - chain:  d = fma(-dd_{t+1}, D[v_{t+1},v_t], pre0);  dd = d * wiv
//   - pre for t-1: fma(-dd_{t+1}, D[v_{t+1},v_{t-1}], Dq[v_{t-1}] - R)
//   - S-table axpy with dd; ctx += d * wkl
// ALL shared loads for iteration t-1 are issued at iteration t; per-token
// (inv,Dq) fused in a per-block float2 table (query-dependent).
//
// 128 blocks (one per batch) x 64 threads: warp 0 = sem, warp 1 = epi.
// Output projection fused at block end.
// ============================================================================
__global__ void __launch_bounds__(64, 1) scan_kernel(
    const int* __restrict__ seq,
    const float* __restrict__ Wo,
    const float* __restrict__ bo,
    float* __restrict__ out)
{
    extern __shared__ int smem_raw[];
    int*    s_tok  = smem_raw;                     // 2048 ints, v<<8
    float*  s_k    = (float*)(s_tok + SEQLEN);     // 2 * 2048
    float*  s_D    = s_k + 2 * VOC * HALF;         // 2 * 4096
    float2* s_ivdq = (float2*)(s_D + 2 * VOC * VOC); // 2 * 64 (inv, Dq)
    float*  s_ctx  = (float*)(s_ivdq + 2 * VOC);   // 64

    const int b    = blockIdx.x;
    const int tid  = threadIdx.x;
    const int mem  = tid >> 5;                // warp 0 = sem, warp 1 = epi
    const int lane = tid & 31;

    // ---- preamble: fill shared tables (both warps cooperate) ----
    {
        const int4* seq4 = (const int4*)(seq + b * SEQLEN);
        int4* tok4 = (int4*)s_tok;
        for (int i = tid; i < SEQLEN / 4; i += 64) {
            int4 v = seq4[i];
            v.x <<= 8; v.y <<= 8; v.z <<= 8; v.w <<= 8;   // D-row byte offset
            tok4[i] = v;
        }
        float4* k4  = (float4*)s_k;
        const float4* gks4 = (const float4*)g_ks;
        const float4* gke4 = (const float4*)g_ke;
        for (int i = tid; i < VOC * HALF / 4; i += 64) {
            k4[i]                  = gks4[i];
            k4[VOC * HALF / 4 + i] = gke4[i];
        }
        float4* D4 = (float4*)s_D;
        const float4* gDs4 = (const float4*)g_Ds;
        const float4* gDe4 = (const float4*)g_De;
        for (int i = tid; i < VOC * VOC / 4; i += 64) {
            D4[i]                 = gDs4[i];
            D4[VOC * VOC / 4 + i] = gDe4[i];
        }
    }
    __syncthreads();

    // per-block (inv, Dq) fusion: Dq[v] = D[v][vq], vq = query token id
    {
        const int vq = s_tok[SEQLEN - 1] >> 8;
        const float* Dm  = s_D + mem * (VOC * VOC);
        const float* ivg = mem ? g_inv_e : g_inv_s;
        float2* tq = s_ivdq + mem * VOC;
        for (int v = lane; v < VOC; v += 32)
            tq[v] = make_float2(ivg[v], Dm[v * VOC + vq]);
    }
    __syncthreads();

    // byte-offset bases for this memory (s_tok entries are v<<8)
    const char* Db    = (const char*)(s_D + mem * (VOC * VOC)); // row: +o, col: +(o>>6)
    const char* Drb   = Db + lane * 8;                          // float2 row slice
    const char* kb    = (const char*)(s_k + mem * (VOC * HALF)) + lane * 4; // +(o>>1)
    const char* ivdqb = (const char*)(s_ivdq + mem * VOC);      // +(o>>5)

    // recency weight, descending: epi w_t = (t+1)/2048; sem w = 1
    const float winc = mem ? (1.0f / 2048.0f) : 0.0f;

    // ---- prologue (state entering iteration t = 2046) ----
    int o0  = s_tok[2046];
    int om1 = s_tok[2045];

    const float2 q0 = *(const float2*)(ivdqb + (o0 >> 5));
    const float2 q1 = *(const float2*)(ivdqb + (om1 >> 5));
    const float w2046 = mem ? (2047.0f / 2048.0f) : 1.0f;
    const float w2045 = mem ? (2046.0f / 2048.0f) : 1.0f;

    float wiv0   = q0.x * w2046;
    float wkl0   = *(const float*)(kb + (o0 >> 1)) * w2046;
    float wiv_m1 = q1.x * w2045;
    float wkl_m1 = *(const float*)(kb + (om1 >> 1)) * w2045;

    float pre0  = q0.y;          // Dq[v_2046] - S_2048 - 0
    float Dq_m1 = q1.y;
    float R_m1  = 0.0f;          // S_2048[v_2045] = 0
    float dd_lag = 0.0f;         // dd_2047 = 0

    float Dc  = 0.0f;            // irrelevant (dd_lag = 0)
    float Dbx = 0.0f;            // irrelevant
    float2 Drow = *(const float2*)(Drb + o0);  // D row of v_2046 (this lane)

    float wt2 = mem ? (2045.0f / 2048.0f) : 1.0f;  // premult weight for t-2

    float Slo = 0.0f, Shi = 0.0f;
    float ctx = 0.0f;

    #pragma unroll 4
    for (int t = 2046; t >= 0; --t) {
        const int tm2 = (t >= 2) ? (t - 2) : 0;
        const int om2 = s_tok[tm2];

        // S lookup for token t-2 against PRE-update S (= S_{t+1})
        const float sv   = ((om2 >> 8) & 1) ? Shi : Slo;
        const float R_m2 = __shfl_sync(0xffffffffu, sv, om2 >> 9);

        // prefetch token t-2 scalars
        const float2 q2  = *(const float2*)(ivdqb + (om2 >> 5));   // (inv, Dq)
        const float  kl2 = *(const float*)(kb + (om2 >> 1));

        // prefetch next iteration's chain operands (all indices known now)
        const float  Dc_n   = *(const float*)(Db + o0 + (om1 >> 6)); // D[v_t, v_{t-1}]
        const float  Dbx_n  = *(const float*)(Db + o0 + (om2 >> 6)); // D[v_t, v_{t-2}]
        const float2 Drow_n = *(const float2*)(Drb + om1);           // row of v_{t-1}

        // ---- critical chain: finalize token t ----
        const float d  = fmaf(-dd_lag, Dc, pre0);   // = Dq - S_t[v_t]... wait: = d_t
        const float dd = d * wiv0;
        ctx = fmaf(d, wkl0, ctx);

        // pre for token t-1 (off-chain: inputs from previous iteration)
        const float A      = Dq_m1 - R_m1;
        const float pre_m1 = fmaf(-dd_lag, Dbx, A);

        // S-table axpy with token t's dd (shfl above read pre-update values)
        Slo = fmaf(dd, Drow.x, Slo);
        Shi = fmaf(dd, Drow.y, Shi);

        // premultiplies for token t-2 (off-chain)
        const float wiv2 = q2.x * wt2;
        const float wkl2 = kl2 * wt2;
        wt2 -= winc;

        // rotate
        Dc = Dc_n; Dbx = Dbx_n; Drow = Drow_n;
        pre0 = pre_m1;
        dd_lag = dd;
        Dq_m1 = q2.y;
        R_m1  = R_m2;
        wiv0 = wiv_m1; wiv_m1 = wiv2;
        wkl0 = wkl_m1; wkl_m1 = wkl2;
        o0 = om1; om1 = om2;
    }

    s_ctx[mem * HALF + lane] = ctx;
    __syncthreads();

    // out[b] = [ctx_s, ctx_e] @ Wo + bo   (64 threads, one column each)
    {
        float o = bo[tid];
        #pragma unroll
        for (int i = 0; i < 2 * HALF; i++)
            o = fmaf(s_ctx[i], Wo[i * VOC + tid], o);
        out[b * VOC + tid] = o;
    }
}

// ============================================================================
// Launch. Inputs in metadata order:
// 0:seq 1:embed 2:W1 3:b1 4:W2 5:b2 6:ln_g 7:ln_b 8:Ws 9:bs 10:We 11:be 12:Wo 13:bo
// ============================================================================
#define SCAN_SMEM_BYTES ((SEQLEN + 2*VOC*HALF + 2*VOC*VOC + 4*VOC + VOC) * 4)

extern "C" void kernel_launch(void* const* d_in, const int* in_sizes, int n_in,
                              void* d_out, int out_size)
{
    const int*   seq   = (const int*)  d_in[0];
    const float* embed = (const float*)d_in[1];
    const float* W1    = (const float*)d_in[2];
    const float* b1    = (const float*)d_in[3];
    const float* W2    = (const float*)d_in[4];
    const float* b2    = (const float*)d_in[5];
    const float* ln_g  = (const float*)d_in[6];
    const float* ln_b  = (const float*)d_in[7];
    const float* Ws    = (const float*)d_in[8];
    const float* bs    = (const float*)d_in[9];
    const float* We    = (const float*)d_in[10];
    const float* be    = (const float*)d_in[11];
    const float* Wo    = (const float*)d_in[12];
    const float* bo    = (const float*)d_in[13];

    cudaFuncSetAttribute(scan_kernel,
                         cudaFuncAttributeMaxDynamicSharedMemorySize,
                         SCAN_SMEM_BYTES);

    precompute_kernel<<<VOC, 128>>>(embed, W1, b1, W2, b2, ln_g, ln_b,
                                    Ws, bs, We, be);
    dots_kernel<<<VOC, 128>>>();
    scan_kernel<<<BATCH, 64, SCAN_SMEM_BYTES>>>(seq, Wo, bo, (float*)d_out);
}

// round 8
// speedup vs baseline: 2.4902x; 1.1828x over previous
#include <cuda_runtime.h>

#define HD     64
#define VOC    64
#define HALF   32
#define BATCH  128
#define SEQLEN 2048

// ---- scratch tables (device globals; no allocation allowed) ----
__device__ __align__(16) float g_ks[VOC * HALF];
__device__ __align__(16) float g_ke[VOC * HALF];
__device__ __align__(16) float g_inv_s[VOC];
__device__ __align__(16) float g_inv_e[VOC];
__device__ __align__(16) float g_Ds[VOC * VOC];   // D[v1][v2] = ks(v1).ks(v2)
__device__ __align__(16) float g_De[VOC * VOC];   // D[v1][v2] = ke(v1).ke(v2)

// ============================================================================
// Kernel A: per-vocab-id table precompute (h depends only on token id).
// ============================================================================
__global__ void precompute_kernel(
    const float* __restrict__ embed,
    const float* __restrict__ W1, const float* __restrict__ b1,
    const float* __restrict__ W2, const float* __restrict__ b2,
    const float* __restrict__ ln_g, const float* __restrict__ ln_b,
    const float* __restrict__ Ws, const float* __restrict__ bs,
    const float* __restrict__ We, const float* __restrict__ be)
{
    const int v = blockIdx.x;
    const int t = threadIdx.x;

    __shared__ float s_e[HD];
    __shared__ float s_a[2 * HD];
    __shared__ float s_x[HD];
    __shared__ float s_h[HD];
    __shared__ float s_kv[2 * HALF];

    if (t < HD) s_e[t] = embed[v * HD + t];
    __syncthreads();

    {   // hidden = relu(e @ W1 + b1), 128 units, one per thread
        float acc = b1[t];
        #pragma unroll
        for (int d = 0; d < HD; d++)
            acc = fmaf(s_e[d], W1[d * (2 * HD) + t], acc);
        s_a[t] = fmaxf(acc, 0.0f);
    }
    __syncthreads();

    if (t < HD) {   // ff = hidden @ W2 + b2 ; x = e + ff
        float f = b2[t];
        #pragma unroll
        for (int k = 0; k < 2 * HD; k++)
            f = fmaf(s_a[k], W2[k * HD + t], f);
        s_x[t] = s_e[t] + f;
    }
    __syncthreads();

    if (t < HD) {   // LayerNorm (redundant per thread — tiny)
        float mu = 0.0f;
        #pragma unroll
        for (int d = 0; d < HD; d++) mu += s_x[d];
        mu *= (1.0f / HD);
        float var = 0.0f;
        #pragma unroll
        for (int d = 0; d < HD; d++) {
            float dd = s_x[d] - mu;
            var = fmaf(dd, dd, var);
        }
        var *= (1.0f / HD);
        float r = 1.0f / sqrtf(var + 1e-5f);
        s_h[t] = fmaf((s_x[t] - mu) * r, ln_g[t], ln_b[t]);
    }
    __syncthreads();

    if (t < HALF) {             // k_sem = h @ Ws + bs
        float k = bs[t];
        #pragma unroll
        for (int d = 0; d < HD; d++)
            k = fmaf(s_h[d], Ws[d * HALF + t], k);
        g_ks[v * HALF + t] = k;
        s_kv[t] = k;
    } else if (t < 2 * HALF) {  // k_epi = h @ We + be
        const int j = t - HALF;
        float k = be[j];
        #pragma unroll
        for (int d = 0; d < HD; d++)
            k = fmaf(s_h[d], We[d * HALF + j], k);
        g_ke[v * HALF + j] = k;
        s_kv[t] = k;
    }
    __syncthreads();

    if (t == 0) {               // 1/(k.k + 1e-6)
        float den = 1e-6f;
        #pragma unroll
        for (int j = 0; j < HALF; j++) den = fmaf(s_kv[j], s_kv[j], den);
        g_inv_s[v] = 1.0f / den;
    } else if (t == 1) {
        float den = 1e-6f;
        #pragma unroll
        for (int j = 0; j < HALF; j++) den = fmaf(s_kv[HALF + j], s_kv[HALF + j], den);
        g_inv_e[v] = 1.0f / den;
    }
}

// ============================================================================
// Kernel A2: token-pair dot tables D[v1][v2] = k(v1).k(v2) per memory.
// ============================================================================
__global__ void dots_kernel()
{
    const int v1  = blockIdx.x;
    const int tid = threadIdx.x;
    const int v2  = tid & 63;
    const int mem = tid >> 6;

    const float* tab = mem ? g_ke : g_ks;
    float d = 0.0f;
    #pragma unroll
    for (int j = 0; j < HALF; j++)
        d = fmaf(tab[v1 * HALF + j], tab[v2 * HALF + j], d);
    (mem ? g_De : g_Ds)[v1 * VOC + v2] = d;
}

// ============================================================================
// Kernel B: backward adjoint scan, depth-4 token ring.
// Every LDS in the loop has its consumer >= 1 iteration later, and every LDS
// address comes from a register >= 1 iteration old — the warp never waits on
// shared-memory latency, making the loop issue-bound (~30 instr/iter).
//
// ctx = sum_t w_t d_t k(v_t),  d_t = Dq[v_t] - S_{t+1}[v_t],
// S_tau[v] = sum_{s>=tau} dd_s D[v_s, v],  dd_s = w_s inv_s d_s.
// S held as 64 scalars (2/lane, Slo/Shi); lookups via shfl lagged 2 iters and
// corrected with two D entries on the way (pre0 chain).
//
// 128 blocks (one per batch) x 64 threads: warp 0 = sem, warp 1 = epi.
// Output projection fused at block end.
// ============================================================================
__global__ void __launch_bounds__(64, 1) scan_kernel(
    const int* __restrict__ seq,
    const float* __restrict__ Wo,
    const float* __restrict__ bo,
    float* __restrict__ out)
{
    extern __shared__ int smem_raw[];
    int*    s_tokp = smem_raw;                       // 8-pad + 2048 (v<<8)
    int*    s_tok  = s_tokp + 8;
    float*  s_k    = (float*)(s_tok + SEQLEN);       // 2 * 2048
    float*  s_D    = s_k + 2 * VOC * HALF;           // 2 * 4096
    float2* s_ivdq = (float2*)(s_D + 2 * VOC * VOC); // 2 * 64 (inv, Dq)
    float*  s_ctx  = (float*)(s_ivdq + 2 * VOC);     // 64

    const int b    = blockIdx.x;
    const int tid  = threadIdx.x;
    const int mem  = tid >> 5;                // warp 0 = sem, warp 1 = epi
    const int lane = tid & 31;

    // ---- preamble: fill shared tables (both warps cooperate) ----
    {
        const int4* seq4 = (const int4*)(seq + b * SEQLEN);
        int4* tok4 = (int4*)s_tok;            // s_tok is 32B-aligned (8 ints pad)
        for (int i = tid; i < SEQLEN / 4; i += 64) {
            int4 v = seq4[i];
            v.x <<= 8; v.y <<= 8; v.z <<= 8; v.w <<= 8;   // D-row byte offset
            tok4[i] = v;
        }
        if (tid < 8) s_tokp[tid] = 0;         // pad: valid v=0 offsets (dead state)
        float4* k4  = (float4*)s_k;
        const float4* gks4 = (const float4*)g_ks;
        const float4* gke4 = (const float4*)g_ke;
        for (int i = tid; i < VOC * HALF / 4; i += 64) {
            k4[i]                  = gks4[i];
            k4[VOC * HALF / 4 + i] = gke4[i];
        }
        float4* D4 = (float4*)s_D;
        const float4* gDs4 = (const float4*)g_Ds;
        const float4* gDe4 = (const float4*)g_De;
        for (int i = tid; i < VOC * VOC / 4; i += 64) {
            D4[i]                 = gDs4[i];
            D4[VOC * VOC / 4 + i] = gDe4[i];
        }
    }
    __syncthreads();

    // per-block (inv, Dq) fusion: Dq[v] = D[v][vq], vq = query token id
    {
        const int vq = s_tok[SEQLEN - 1] >> 8;
        const float* Dm  = s_D + mem * (VOC * VOC);
        const float* ivg = mem ? g_inv_e : g_inv_s;
        float2* tq = s_ivdq + mem * VOC;
        for (int v = lane; v < VOC; v += 32)
            tq[v] = make_float2(ivg[v], Dm[v * VOC + vq]);
    }
    __syncthreads();

    // byte-offset bases for this memory (s_tok entries are v<<8)
    const char* Db    = (const char*)(s_D + mem * (VOC * VOC)); // row +o, col +(o>>6)
    const char* Drb   = Db + lane * 8;                          // float2 row slice
    const char* kb    = (const char*)(s_k + mem * (VOC * HALF)) + lane * 4; // +(o>>1)
    const char* ivdqb = (const char*)(s_ivdq + mem * VOC);      // +(o>>5)

    // recency weight, descending: epi w_t = (t+1)/2048; sem w = 1
    const float winc = mem ? (1.0f / 2048.0f) : 0.0f;

    // ---- prologue: state entering iteration t = 2046 ----
    int o0  = s_tok[2046];
    int om1 = s_tok[2045];
    int om2 = s_tok[2044];
    int om3 = s_tok[2043];

    const float2 qa = *(const float2*)(ivdqb + (o0 >> 5));
    const float2 qb = *(const float2*)(ivdqb + (om1 >> 5));
    const float w0v = mem ? (2047.0f / 2048.0f) : 1.0f;
    const float w1v = mem ? (2046.0f / 2048.0f) : 1.0f;

    float wiv0   = qa.x * w0v;
    float wkl0   = *(const float*)(kb + (o0 >> 1)) * w0v;
    float wiv_m1 = qb.x * w1v;
    float wkl_m1 = *(const float*)(kb + (om1 >> 1)) * w1v;

    float pre0  = qa.y;          // d_2046 = Dq[v_2046] (S_2048 = 0)
    float Dq_m1 = qb.y;
    float R_m1  = 0.0f;          // S_2048[v_2045] = 0
    float dd_lag = 0.0f;         // dd_2047 = 0

    float Dc  = 0.0f;            // irrelevant (dd_lag = 0)
    float Dbx = 0.0f;            // irrelevant
    float2 Drow = *(const float2*)(Drb + o0);  // D row of v_2046 (this lane)

    // q/kl staging register: token t-2 of the first iteration (v_2044)
    float2 q_c  = *(const float2*)(ivdqb + (om2 >> 5));
    float  kl_c = *(const float*)(kb + (om2 >> 1));
    float wt2 = mem ? (2045.0f / 2048.0f) : 1.0f;  // weight for token t-2

    const int* ptok = s_tok + 2042;              // &tok[t-4] at t = 2046

    float Slo = 0.0f, Shi = 0.0f;
    float ctx = 0.0f;

    #pragma unroll 4
    for (int t = 2046; t >= 0; --t) {
        // (1) token prefetch, no consumer this iteration
        const int om4 = *ptok;
        --ptok;

        // (2) S lookup for token t-2 against pre-update S (= S_{t+1})
        const float sv   = ((om2 >> 8) & 1) ? Shi : Slo;
        const float R_m2 = __shfl_sync(0xffffffffu, sv, om2 >> 9);

        // (3) q/kl prefetch for token t-3 (consumed next iteration)
        const float2 q_n  = *(const float2*)(ivdqb + (om3 >> 5));
        const float  kl_n = *(const float*)(kb + (om3 >> 1));

        // (4) chain operands for iteration t-1 (consumed next iteration)
        const float  Dc_n   = *(const float*)(Db + o0 + (om1 >> 6)); // D[v_t,v_{t-1}]
        const float  Dbx_n  = *(const float*)(Db + o0 + (om2 >> 6)); // D[v_t,v_{t-2}]
        const float2 Drow_n = *(const float2*)(Drb + om1);           // row v_{t-1}

        // (5) critical chain: finalize token t
        const float d  = fmaf(-dd_lag, Dc, pre0);    // d_t
        const float dd = d * wiv0;                   // dd_t
        ctx = fmaf(d, wkl0, ctx);

        // (6) pre for token t-1 (off-chain)
        const float A      = Dq_m1 - R_m1;
        const float pre_m1 = fmaf(-dd_lag, Dbx, A);

        // (7) S-table axpy (shfl above read pre-update values)
        Slo = fmaf(dd, Drow.x, Slo);
        Shi = fmaf(dd, Drow.y, Shi);

        // (8) premultiplies for token t-2 from LAST iteration's q/kl loads
        const float wiv2 = q_c.x * wt2;
        const float wkl2 = kl_c * wt2;
        const float Dq2  = q_c.y;
        wt2 -= winc;

        // (9) rotate
        Dc = Dc_n; Dbx = Dbx_n; Drow = Drow_n;
        pre0 = pre_m1;
        dd_lag = dd;
        Dq_m1 = Dq2;
        R_m1  = R_m2;
        wiv0 = wiv_m1; wiv_m1 = wiv2;
        wkl0 = wkl_m1; wkl_m1 = wkl2;
        q_c = q_n; kl_c = kl_n;
        o0 = om1; om1 = om2; om2 = om3; om3 = om4;
    }

    s_ctx[mem * HALF + lane] = ctx;
    __syncthreads();

    // out[b] = [ctx_s, ctx_e] @ Wo + bo   (64 threads, one column each)
    {
        float o = bo[tid];
        #pragma unroll
        for (int i = 0; i < 2 * HALF; i++)
            o = fmaf(s_ctx[i], Wo[i * VOC + tid], o);
        out[b * VOC + tid] = o;
    }
}

// ============================================================================
// Launch. Inputs in metadata order:
// 0:seq 1:embed 2:W1 3:b1 4:W2 5:b2 6:ln_g 7:ln_b 8:Ws 9:bs 10:We 11:be 12:Wo 13:bo
// ============================================================================
#define SCAN_SMEM_BYTES ((8 + SEQLEN + 2*VOC*HALF + 2*VOC*VOC + 4*VOC + VOC) * 4)

extern "C" void kernel_launch(void* const* d_in, const int* in_sizes, int n_in,
                              void* d_out, int out_size)
{
    const int*   seq   = (const int*)  d_in[0];
    const float* embed = (const float*)d_in[1];
    const float* W1    = (const float*)d_in[2];
    const float* b1    = (const float*)d_in[3];
    const float* W2    = (const float*)d_in[4];
    const float* b2    = (const float*)d_in[5];
    const float* ln_g  = (const float*)d_in[6];
    const float* ln_b  = (const float*)d_in[7];
    const float* Ws    = (const float*)d_in[8];
    const float* bs    = (const float*)d_in[9];
    const float* We    = (const float*)d_in[10];
    const float* be    = (const float*)d_in[11];
    const float* Wo    = (const float*)d_in[12];
    const float* bo    = (const float*)d_in[13];

    cudaFuncSetAttribute(scan_kernel,
                         cudaFuncAttributeMaxDynamicSharedMemorySize,
                         SCAN_SMEM_BYTES);

    precompute_kernel<<<VOC, 128>>>(embed, W1, b1, W2, b2, ln_g, ln_b,
                                    Ws, bs, We, be);
    dots_kernel<<<VOC, 128>>>();
    scan_kernel<<<BATCH, 64, SCAN_SMEM_BYTES>>>(seq, Wo, bo, (float*)d_out);
}